// round 1
// baseline (speedup 1.0000x reference)
#include <cuda_runtime.h>
#include <cuda_bf16.h>

// BradleyTerryModel: loss = -sum_{i!=j} W[i,j] * (b_i - logaddexp(b_i, b_j)), N=8192
//
// logp(i,j) = min(d,0) - log1p(exp(-|d|)),  d = b_i - b_j
// Full-matrix sum S includes diagonal terms W[ii]*(-ln2); corrected in finalize:
//   loss = -S - ln2 * sum_i W[ii]

#define NN      8192
#define NV4     2048                 // NN/4
#define TOTAL4  (NN * NV4)           // 16,777,216 float4 elements of W
#define BLOCKS  1184                 // 8 blocks/SM * 148 SMs
#define THREADS 256
#define STRIDE  (BLOCKS * THREADS)

__device__ double g_partials[BLOCKS];

__device__ __forceinline__ float bt_term(float bi, float bj) {
    float d = bi - bj;
    float m = fminf(d, 0.0f);
    float u = __expf(-fabsf(d));      // FMUL(log2e) + MUFU.EX2
    return m - __logf(1.0f + u);      // FADD + MUFU.LG2 + FFMA(ln2)
}

__global__ __launch_bounds__(THREADS)
void bt_main(const float* __restrict__ W, const float* __restrict__ B) {
    const float4* __restrict__ W4 = reinterpret_cast<const float4*>(W);
    const float4* __restrict__ B4 = reinterpret_cast<const float4*>(B);

    int tid = blockIdx.x * THREADS + threadIdx.x;
    float acc = 0.0f;   // all terms are <= 0: same-sign accumulation, no cancellation

    #pragma unroll 4
    for (int idx = tid; idx < TOTAL4; idx += STRIDE) {
        int i = idx >> 11;                 // row index (N/4 = 2048 = 2^11 float4s per row)
        int c = idx & (NV4 - 1);           // float4-column within row
        float4 w  = W4[idx];
        float4 bj = B4[c];
        float  bi = __ldg(B + i);
        acc += w.x * bt_term(bi, bj.x);
        acc += w.y * bt_term(bi, bj.y);
        acc += w.z * bt_term(bi, bj.z);
        acc += w.w * bt_term(bi, bj.w);
    }

    __shared__ double sm[THREADS];
    sm[threadIdx.x] = (double)acc;
    __syncthreads();
    #pragma unroll
    for (int s = THREADS / 2; s > 0; s >>= 1) {
        if (threadIdx.x < s) sm[threadIdx.x] += sm[threadIdx.x + s];
        __syncthreads();
    }
    if (threadIdx.x == 0) g_partials[blockIdx.x] = sm[0];
}

__global__ __launch_bounds__(256)
void bt_finalize(const float* __restrict__ W, float* __restrict__ out) {
    int t = threadIdx.x;

    // Sum block partials (fixed order -> deterministic)
    double s = 0.0;
    for (int k = t; k < BLOCKS; k += 256) s += g_partials[k];

    // Diagonal correction: sum_i W[i,i]
    double dsum = 0.0;
    for (int i = t; i < NN; i += 256) dsum += (double)W[(size_t)i * NN + i];

    __shared__ double sm[256];
    sm[t] = s + 0.6931471805599453 * dsum;  // S_full + ln2 * sum(W_ii)
    __syncthreads();
    #pragma unroll
    for (int r = 128; r > 0; r >>= 1) {
        if (t < r) sm[t] += sm[t + r];
        __syncthreads();
    }
    if (t == 0) out[0] = (float)(-sm[0]);   // loss = -(S_full + ln2 * sum W_ii)
}

extern "C" void kernel_launch(void* const* d_in, const int* in_sizes, int n_in,
                              void* d_out, int out_size) {
    const float* W = (const float*)d_in[0];   // win_matrix [8192, 8192] f32
    const float* B = (const float*)d_in[1];   // betas [8192] f32
    float* out = (float*)d_out;

    bt_main<<<BLOCKS, THREADS>>>(W, B);
    bt_finalize<<<1, 256>>>(W, out);
}

// round 2
// speedup vs baseline: 1.0835x; 1.0835x over previous
#include <cuda_runtime.h>
#include <cuda_bf16.h>

// BradleyTerryModel: loss = -sum_{i!=j} W[i,j] * (b_i - logaddexp(b_i, b_j)), N=8192
//
// logp(i,j) = min(d,0) - log1p(exp(-|d|)),  d = b_i - b_j
// Diagonal (i==j) terms excluded in-loop via select (w zeroed).
// Single kernel: grid-stride sum -> per-block double partial -> last block
// reduces partials in fixed order (deterministic) and writes the scalar.

#define NN      8192
#define NV4     2048                 // NN/4
#define TOTAL4  (NN * NV4)           // 16,777,216 float4 elements of W
#define BLOCKS  1184                 // 8 blocks/SM * 148 SMs
#define THREADS 256
#define STRIDE  (BLOCKS * THREADS)

__device__ double       g_partials[BLOCKS];
__device__ unsigned int g_count;     // zero-initialized at module load; reset by last block

__device__ __forceinline__ float bt_term(float bi, float bj) {
    float d = bi - bj;
    float m = fminf(d, 0.0f);
    float u = __expf(-fabsf(d));      // FMUL(log2e) + MUFU.EX2
    return m - __logf(1.0f + u);      // FADD + MUFU.LG2 + FFMA(ln2)
}

__global__ __launch_bounds__(THREADS)
void bt_main(const float* __restrict__ W, const float* __restrict__ B,
             float* __restrict__ out) {
    const float4* __restrict__ W4 = reinterpret_cast<const float4*>(W);
    const float4* __restrict__ B4 = reinterpret_cast<const float4*>(B);

    int tid = blockIdx.x * THREADS + threadIdx.x;
    float acc = 0.0f;   // all kept terms are <= 0: same-sign accumulation

    #pragma unroll 4
    for (int idx = tid; idx < TOTAL4; idx += STRIDE) {
        int i  = idx >> 11;                // row (2048 float4s per row)
        int c  = idx & (NV4 - 1);          // float4-column within row
        int j0 = c << 2;                   // scalar column of .x
        float4 w  = W4[idx];
        float4 bj = B4[c];
        float  bi = __ldg(B + i);
        // zero the diagonal weight instead of a separate correction pass
        float w0 = (i == j0    ) ? 0.0f : w.x;
        float w1 = (i == j0 + 1) ? 0.0f : w.y;
        float w2 = (i == j0 + 2) ? 0.0f : w.z;
        float w3 = (i == j0 + 3) ? 0.0f : w.w;
        acc += w0 * bt_term(bi, bj.x);
        acc += w1 * bt_term(bi, bj.y);
        acc += w2 * bt_term(bi, bj.z);
        acc += w3 * bt_term(bi, bj.w);
    }

    __shared__ double sm[THREADS];
    sm[threadIdx.x] = (double)acc;
    __syncthreads();
    #pragma unroll
    for (int s = THREADS / 2; s > 0; s >>= 1) {
        if (threadIdx.x < s) sm[threadIdx.x] += sm[threadIdx.x + s];
        __syncthreads();
    }

    // last-block-done reduction (threadfence-reduction pattern)
    __shared__ bool is_last;
    if (threadIdx.x == 0) {
        g_partials[blockIdx.x] = sm[0];
        __threadfence();
        unsigned v = atomicAdd(&g_count, 1u);
        is_last = (v == (unsigned)(BLOCKS - 1));
    }
    __syncthreads();

    if (is_last) {
        __threadfence();
        double s = 0.0;                       // fixed-order -> deterministic
        for (int k = threadIdx.x; k < BLOCKS; k += THREADS) s += g_partials[k];
        sm[threadIdx.x] = s;
        __syncthreads();
        #pragma unroll
        for (int r = THREADS / 2; r > 0; r >>= 1) {
            if (threadIdx.x < r) sm[threadIdx.x] += sm[threadIdx.x + r];
            __syncthreads();
        }
        if (threadIdx.x == 0) {
            out[0] = (float)(-sm[0]);
            g_count = 0;                      // reset for next graph replay
        }
    }
}

extern "C" void kernel_launch(void* const* d_in, const int* in_sizes, int n_in,
                              void* d_out, int out_size) {
    const float* W = (const float*)d_in[0];   // win_matrix [8192, 8192] f32
    const float* B = (const float*)d_in[1];   // betas [8192] f32
    float* out = (float*)d_out;

    bt_main<<<BLOCKS, THREADS>>>(W, B, out);
}